// round 4
// baseline (speedup 1.0000x reference)
#include <cuda_runtime.h>

#define K 64
#define N 128
#define NPAIR 2016            // C(64,2)
#define NCAND (1 + K + NPAIR) // 2081
#define LLR_MAX 100.0f

__global__ __launch_bounds__(128) void osd_kernel(
    const float* __restrict__ llrs,
    const float* __restrict__ gm,
    float* __restrict__ out)
{
    const int b = blockIdx.x;
    const int t = threadIdx.x;

    __shared__ float s_llr[N];        // clipped llr, original order
    __shared__ float s_llr_sort[N];   // llr in sorted order
    __shared__ int   s_idx_sort[N];   // sorted pos -> original index
    __shared__ unsigned s_gm_bits[K][4]; // gm rows as 128-bit masks (orig col order)
    __shared__ int   s_pivot[K];
    __shared__ int   s_mark[N];
    __shared__ int   s_parity[K];     // non-pivot sorted positions, ascending
    __shared__ float s_L[K];          // llr at pivot positions
    __shared__ float s_pen[K];        // |L_i|
    __shared__ float s_Lp[K];         // llr at parity positions
    __shared__ unsigned long long s_pp[K]; // parity part of each MRB row (64 bits)
    __shared__ float s_lut[8 * 256];  // byte LUTs for parity correlation
    __shared__ float s_bv[128];
    __shared__ int   s_bq[128];
    __shared__ unsigned long long s_rlo, s_rhi, s_pw0, s_u, s_mwin, s_pwin;
    __shared__ float s_base;
    __shared__ int   s_p;

    // ---- load + clip llr ----
    float v = llrs[b * N + t];
    v = fminf(fmaxf(v, -LLR_MAX), LLR_MAX);
    s_llr[t] = v;
    __syncthreads();

    // ---- stable argsort by descending |llr| (O(n^2) rank) ----
    {
        float a = fabsf(v);
        int rank = 0;
        #pragma unroll 8
        for (int j = 0; j < N; j++) {
            float aj = fabsf(s_llr[j]);
            rank += (aj > a) ? 1 : ((aj == a && j < t) ? 1 : 0);
        }
        s_idx_sort[rank] = t;
        s_llr_sort[rank] = v;
    }

    // ---- pack gm rows into bitmasks (coalesced, via ballot) ----
    {
        const int w = t >> 5;
        for (int r = 0; r < K; r++) {
            float g = gm[r * N + t];
            unsigned m = __ballot_sync(0xffffffffu, g > 0.5f);
            if ((t & 31) == 0) s_gm_bits[r][w] = m;
        }
    }
    __syncthreads();

    // ---- build column-permuted rows, thread r owns row r in (lo,hi) ----
    unsigned long long lo = 0ull, hi = 0ull;
    if (t < K) {
        #pragma unroll 4
        for (int pos = 0; pos < N; pos++) {
            int idx = s_idx_sort[pos];
            unsigned long long bit = (s_gm_bits[t][idx >> 5] >> (idx & 31)) & 1u;
            if (pos < 64) lo |= bit << pos;
            else          hi |= bit << (pos - 64);
        }
    }
    __syncthreads();

    // ---- Gauss-Jordan over GF(2), matching reference scan semantics ----
    for (int i = 0; i < K; i++) {
        if (t == i) {
            int p;
            if (lo)      p = __ffsll(lo) - 1;
            else if (hi) p = 64 + __ffsll(hi) - 1;
            else         p = 0; // argmax of all-zero row -> 0 (never happens, full rank)
            s_p = p; s_rlo = lo; s_rhi = hi; s_pivot[i] = p;
        }
        __syncthreads();
        if (t < K && t != i) {
            int p = s_p;
            unsigned long long bit = (p < 64) ? (lo >> p) : (hi >> (p - 64));
            if (bit & 1ull) { lo ^= s_rlo; hi ^= s_rhi; }
        }
        __syncthreads();
    }

    // ---- pivot marks, parity (non-pivot) positions ascending ----
    s_mark[t] = 0;
    __syncthreads();
    if (t < K) s_mark[s_pivot[t]] = 1;
    __syncthreads();
    if (t == 0) {
        int c = 0;
        for (int pos = 0; pos < N; pos++)
            if (!s_mark[pos]) s_parity[c++] = pos;
    }
    __syncthreads();

    // ---- L, Lp, parity-part bitmasks ----
    if (t < K) {
        float Li = s_llr_sort[s_pivot[t]];
        s_L[t]   = Li;
        s_pen[t] = fabsf(Li);
        s_Lp[t]  = s_llr_sort[s_parity[t]];
        unsigned long long pp = 0ull;
        #pragma unroll 4
        for (int j = 0; j < K; j++) {
            int pos = s_parity[j];
            unsigned long long bit = (pos < 64) ? (lo >> pos) : (hi >> (pos - 64));
            pp |= (bit & 1ull) << j;
        }
        s_pp[t] = pp;
    }
    __syncthreads();

    // ---- baseline: u = (L>0), base msg corr, baseline parity word ----
    if (t == 0) {
        float base = 0.0f;
        unsigned long long pw0 = 0ull, u = 0ull;
        for (int i = 0; i < K; i++) {
            if (s_L[i] > 0.0f) { base += s_L[i]; pw0 ^= s_pp[i]; u |= 1ull << i; }
        }
        s_base = base; s_pw0 = pw0; s_u = u;
    }
    __syncthreads();

    // ---- byte LUTs: lut[tbl*256 + b] = sum of Lp[tbl*8 + bits(b)] ----
    for (int e = t; e < 2048; e += 128) {
        int tbl = e >> 8;
        unsigned bb = e & 255u;
        float s = 0.0f;
        while (bb) {
            int bpos = __ffs(bb) - 1;
            s += s_Lp[tbl * 8 + bpos];
            bb &= bb - 1;
        }
        s_lut[e] = s;
    }
    __syncthreads();

    // ---- candidate scan: argmax correlation (== argmin reference distance) ----
    const float base = s_base;
    const unsigned long long pw0 = s_pw0;
    float bestv = -3.0e38f;
    int   bestq = 0x7fffffff;
    for (int q = t; q < NCAND; q += 128) {
        float msg;
        unsigned long long pw;
        if (q == 0) {
            msg = base; pw = pw0;
        } else if (q <= K) {
            int i = q - 1;
            msg = base - s_pen[i];
            pw  = pw0 ^ s_pp[i];
        } else {
            int r = q - (K + 1);
            int i = 0, c = K - 1;
            while (r >= c) { r -= c; c--; i++; }
            int j = i + 1 + r;
            msg = base - s_pen[i] - s_pen[j];
            pw  = pw0 ^ s_pp[i] ^ s_pp[j];
        }
        float s = msg;
        #pragma unroll
        for (int bkt = 0; bkt < 8; bkt++)
            s += s_lut[bkt * 256 + (int)((pw >> (bkt * 8)) & 0xffull)];
        if (s > bestv) { bestv = s; bestq = q; } // strictly-greater keeps earliest q
    }
    s_bv[t] = bestv;
    s_bq[t] = bestq;
    __syncthreads();

    // ---- reduce with first-index tiebreak, decode winner ----
    if (t == 0) {
        float bv = s_bv[0]; int bq = s_bq[0];
        for (int j = 1; j < 128; j++) {
            if (s_bv[j] > bv || (s_bv[j] == bv && s_bq[j] < bq)) {
                bv = s_bv[j]; bq = s_bq[j];
            }
        }
        unsigned long long flips = 0ull;
        if (bq >= 1 && bq <= K) {
            flips = 1ull << (bq - 1);
        } else if (bq > K) {
            int r = bq - (K + 1);
            int i = 0, c = K - 1;
            while (r >= c) { r -= c; c--; i++; }
            int j = i + 1 + r;
            flips = (1ull << i) | (1ull << j);
        }
        unsigned long long pw = s_pw0;
        unsigned long long f = flips;
        while (f) {
            int i = __ffsll(f) - 1;
            pw ^= s_pp[i];
            f &= f - 1;
        }
        s_mwin = s_u ^ flips;
        s_pwin = pw;
    }
    __syncthreads();

    // ---- scatter to original column order (inverse of total permutation) ----
    if (t < K) {
        int orig = s_idx_sort[s_pivot[t]];
        out[b * N + orig] = (float)((s_mwin >> t) & 1ull);
    } else {
        int j = t - K;
        int orig = s_idx_sort[s_parity[j]];
        out[b * N + orig] = (float)((s_pwin >> j) & 1ull);
    }
}

extern "C" void kernel_launch(void* const* d_in, const int* in_sizes, int n_in,
                              void* d_out, int out_size)
{
    const float* llrs = (const float*)d_in[0]; // (bs, 128) float32
    const float* gm   = (const float*)d_in[1]; // (64, 128) float32
    // d_in[2] = t (fixed to 2 for this problem)
    float* out = (float*)d_out;                // (bs, 128) float32

    int bs = in_sizes[0] / N;
    osd_kernel<<<bs, 128>>>(llrs, gm, out);
}

// round 5
// speedup vs baseline: 1.7264x; 1.7264x over previous
#include <cuda_runtime.h>

#define K 64
#define N 128
#define NCAND 2081            // 1 + 64 + C(64,2)
#define LLR_MAX 100.0f
#define FULLMASK 0xffffffffu

__global__ __launch_bounds__(128) void osd_kernel(
    const float* __restrict__ llrs,
    const float* __restrict__ gm,
    float* __restrict__ out)
{
    const int b = blockIdx.x;
    const int t = threadIdx.x;
    const int lane = t & 31;
    const int wid  = t >> 5;

    __shared__ float s_abs[N];
    __shared__ float s_llr_sort[N];
    __shared__ int   s_idx_sort[N];
    __shared__ unsigned long long s_rowlo[K], s_rowhi[K];
    __shared__ int   s_pivot[K];
    __shared__ unsigned s_markw[4];
    __shared__ int   s_parity[K];
    __shared__ float s_pen[K];
    __shared__ float s_Lp[K];
    __shared__ unsigned long long s_pp[K];
    __shared__ float s_lut[8 * 256];
    __shared__ float s_bvw[4];
    __shared__ int   s_bqw[4];
    __shared__ float s_basew[2];
    __shared__ unsigned long long s_pw0w[2];
    __shared__ unsigned s_uw[2];
    __shared__ float s_base;
    __shared__ unsigned long long s_pw0, s_u, s_mwin, s_pwin;

    // ---- load + clip llr ----
    float v = llrs[b * N + t];
    v = fminf(fmaxf(v, -LLR_MAX), LLR_MAX);
    s_abs[t] = fabsf(v);
    if (t < 4) s_markw[t] = 0u;
    __syncthreads();

    // ---- stable argsort by descending |llr| (O(n^2) rank) ----
    {
        float a = s_abs[t];
        int rank = 0;
        #pragma unroll 16
        for (int j = 0; j < N; j++) {
            float aj = s_abs[j];
            rank += (aj > a) || (aj == a && j < t);
        }
        s_idx_sort[rank] = t;
        s_llr_sort[rank] = v;
    }

    // ---- pack gm row t (t<64) with 32 independent float4 loads ----
    unsigned long long glo = 0ull, ghi = 0ull;
    if (t < K) {
        const float4* row = reinterpret_cast<const float4*>(gm + t * N);
        #pragma unroll
        for (int c4 = 0; c4 < 32; c4++) {
            float4 f = row[c4];
            unsigned long long nib =
                  (unsigned long long)(f.x > 0.5f)
                | ((unsigned long long)(f.y > 0.5f) << 1)
                | ((unsigned long long)(f.z > 0.5f) << 2)
                | ((unsigned long long)(f.w > 0.5f) << 3);
            int base = c4 * 4;
            if (base < 64) glo |= nib << base;
            else           ghi |= nib << (base - 64);
        }
    }
    __syncthreads();  // idx_sort ready

    // ---- build column-permuted row directly from registers ----
    if (t < K) {
        unsigned long long plo = 0ull, phi = 0ull;
        #pragma unroll 8
        for (int pos = 0; pos < N; pos++) {
            int idx = s_idx_sort[pos];
            unsigned long long bit = (idx < 64) ? ((glo >> idx) & 1ull)
                                                : ((ghi >> (idx - 64)) & 1ull);
            if (pos < 64) plo |= bit << pos;
            else          phi |= bit << (pos - 64);
        }
        s_rowlo[t] = plo;
        s_rowhi[t] = phi;
    }
    __syncthreads();

    // ---- single-warp register Gauss-Jordan over GF(2) (zero barriers) ----
    // Lane l owns rows l (slot 0) and l+32 (slot 1).
    if (t < 32) {
        unsigned long long r0lo = s_rowlo[t],      r0hi = s_rowhi[t];
        unsigned long long r1lo = s_rowlo[t + 32], r1hi = s_rowhi[t + 32];
        #pragma unroll 1
        for (int i = 0; i < K; i++) {
            const int src  = i & 31;
            const int slot = i >> 5;  // uniform across warp
            unsigned long long plo = __shfl_sync(FULLMASK, slot ? r1lo : r0lo, src);
            unsigned long long phi = __shfl_sync(FULLMASK, slot ? r1hi : r0hi, src);
            int p = plo ? (__ffsll(plo) - 1)
                        : (phi ? (64 + __ffsll(phi) - 1) : 0);
            if (lane == 0) s_pivot[i] = p;
            unsigned long long b0 = (p < 64) ? (r0lo >> p) : (r0hi >> (p - 64));
            unsigned long long b1 = (p < 64) ? (r1lo >> p) : (r1hi >> (p - 64));
            bool piv0 = (t == src) && (slot == 0);
            bool piv1 = (t == src) && (slot == 1);
            if ((b0 & 1ull) && !piv0) { r0lo ^= plo; r0hi ^= phi; }
            if ((b1 & 1ull) && !piv1) { r1lo ^= plo; r1hi ^= phi; }
        }
        s_rowlo[t] = r0lo;      s_rowhi[t] = r0hi;
        s_rowlo[t + 32] = r1lo; s_rowhi[t + 32] = r1hi;
    }
    __syncthreads();

    // ---- mark pivot positions (bitmask via shared atomics) ----
    if (t < K) {
        int p = s_pivot[t];
        atomicOr(&s_markw[p >> 5], 1u << (p & 31));
    }
    __syncthreads();

    // ---- parity positions (prefix popcount, fully parallel) ----
    {
        unsigned w = s_markw[wid];
        bool mk = (w >> lane) & 1u;
        int before = 0;
        #pragma unroll
        for (int ww = 0; ww < 4; ww++)
            if (ww < wid) before += __popc(s_markw[ww]);
        before += __popc(w & ((1u << lane) - 1u));
        if (!mk) s_parity[t - before] = t;
    }
    __syncthreads();

    // ---- L, pen, Lp, pp + warp-reduced baseline ----
    if (t < K) {
        float Lt = s_llr_sort[s_pivot[t]];
        s_pen[t] = fabsf(Lt);
        s_Lp[t]  = s_llr_sort[s_parity[t]];
        unsigned long long rlo = s_rowlo[t], rhi = s_rowhi[t];
        unsigned long long pp = 0ull;
        #pragma unroll 8
        for (int j = 0; j < K; j++) {
            int pos = s_parity[j];
            unsigned long long bit = (pos < 64) ? ((rlo >> pos) & 1ull)
                                                : ((rhi >> (pos - 64)) & 1ull);
            pp |= bit << j;
        }
        s_pp[t] = pp;
        // baseline partials (warps 0 and 1, fully active)
        bool act = Lt > 0.0f;
        float val = act ? Lt : 0.0f;
        unsigned long long px = act ? pp : 0ull;
        #pragma unroll
        for (int o = 16; o > 0; o >>= 1) {
            val += __shfl_down_sync(FULLMASK, val, o);
            px  ^= __shfl_down_sync(FULLMASK, px, o);
        }
        unsigned ub = __ballot_sync(FULLMASK, act);
        if (lane == 0) { s_basew[wid] = val; s_pw0w[wid] = px; s_uw[wid] = ub; }
    }
    __syncthreads();
    if (t == 0) {
        s_base = s_basew[0] + s_basew[1];
        s_pw0  = s_pw0w[0] ^ s_pw0w[1];
        s_u    = (unsigned long long)s_uw[0] | ((unsigned long long)s_uw[1] << 32);
    }

    // ---- byte LUTs: lut[tbl*256 + b] = sum of Lp[tbl*8 + bits(b)] ----
    for (int e = t; e < 2048; e += 128) {
        int tbl = e >> 8;
        unsigned bb = e & 255u;
        float s = 0.0f;
        while (bb) {
            int bp = __ffs(bb) - 1;
            s += s_Lp[tbl * 8 + bp];
            bb &= bb - 1;
        }
        s_lut[e] = s;
    }
    __syncthreads();

    // ---- candidate scan: contiguous q-ranges, incremental (i,j) ----
    const float base = s_base;
    const unsigned long long pw0 = s_pw0;
    // threads 0..32 take 17 candidates, 33..127 take 16  (33*17 + 95*16 = 2081)
    const int cnt = (t < 33) ? 17 : 16;
    int q = t * 16 + min(t, 33);
    float bestv = -3.0e38f;
    int   bestq = 0x7fffffff;
    int pi = 0, pj = 0;
    bool init = false;
    for (int s_i = 0; s_i < cnt; s_i++, q++) {
        float sc;
        unsigned long long pw;
        if (q == 0) {
            sc = base; pw = pw0;
        } else if (q <= K) {
            sc = base - s_pen[q - 1];
            pw = pw0 ^ s_pp[q - 1];
        } else {
            if (!init) {
                int r = q - (K + 1);
                pi = 0; int c = K - 1;
                while (r >= c) { r -= c; c--; pi++; }
                pj = pi + 1 + r;
                init = true;
            } else {
                pj++;
                if (pj == K) { pi++; pj = pi + 1; }
            }
            sc = base - s_pen[pi] - s_pen[pj];
            pw = pw0 ^ s_pp[pi] ^ s_pp[pj];
        }
        #pragma unroll
        for (int bkt = 0; bkt < 8; bkt++)
            sc += s_lut[bkt * 256 + (int)((pw >> (bkt * 8)) & 0xffull)];
        if (sc > bestv) { bestv = sc; bestq = q; }  // strict > keeps earliest q
    }

    // ---- warp reduce (max by (v, -q): total order -> tree-safe) ----
    #pragma unroll
    for (int o = 16; o > 0; o >>= 1) {
        float ov = __shfl_down_sync(FULLMASK, bestv, o);
        int   oq = __shfl_down_sync(FULLMASK, bestq, o);
        if (ov > bestv || (ov == bestv && oq < bestq)) { bestv = ov; bestq = oq; }
    }
    if (lane == 0) { s_bvw[wid] = bestv; s_bqw[wid] = bestq; }
    __syncthreads();

    // ---- final combine + decode winner ----
    if (t == 0) {
        float bv = s_bvw[0]; int bq = s_bqw[0];
        #pragma unroll
        for (int w = 1; w < 4; w++) {
            if (s_bvw[w] > bv || (s_bvw[w] == bv && s_bqw[w] < bq)) {
                bv = s_bvw[w]; bq = s_bqw[w];
            }
        }
        unsigned long long flips = 0ull;
        if (bq >= 1 && bq <= K) {
            flips = 1ull << (bq - 1);
        } else if (bq > K) {
            int r = bq - (K + 1);
            int i2 = 0, c = K - 1;
            while (r >= c) { r -= c; c--; i2++; }
            int j2 = i2 + 1 + r;
            flips = (1ull << i2) | (1ull << j2);
        }
        unsigned long long pw = s_pw0, f = flips;
        while (f) {
            int i2 = __ffsll(f) - 1;
            pw ^= s_pp[i2];
            f &= f - 1;
        }
        s_mwin = s_u ^ flips;
        s_pwin = pw;
    }
    __syncthreads();

    // ---- scatter to original column order ----
    if (t < K) {
        int orig = s_idx_sort[s_pivot[t]];
        out[b * N + orig] = (float)((s_mwin >> t) & 1ull);
    } else {
        int j2 = t - K;
        int orig = s_idx_sort[s_parity[j2]];
        out[b * N + orig] = (float)((s_pwin >> j2) & 1ull);
    }
}

extern "C" void kernel_launch(void* const* d_in, const int* in_sizes, int n_in,
                              void* d_out, int out_size)
{
    const float* llrs = (const float*)d_in[0]; // (bs, 128) float32
    const float* gm   = (const float*)d_in[1]; // (64, 128) float32
    float* out = (float*)d_out;                // (bs, 128) float32
    int bs = in_sizes[0] / N;
    osd_kernel<<<bs, 128>>>(llrs, gm, out);
}

// round 6
// speedup vs baseline: 2.3695x; 1.3725x over previous
#include <cuda_runtime.h>

#define K 64
#define N 128
#define NCAND 2081            // 1 + 64 + C(64,2)
#define LLR_MAX 100.0f
#define FULLMASK 0xffffffffu

__global__ __launch_bounds__(256) void osd_kernel(
    const float* __restrict__ llrs,
    const float* __restrict__ gm,
    float* __restrict__ out)
{
    const int b = blockIdx.x;
    const int t = threadIdx.x;
    const int lane = t & 31;
    const int wid  = t >> 5;

    __shared__ float s_abs[N];
    __shared__ int   s_rank2[N];
    __shared__ float s_llr_sort[N];
    __shared__ int   s_idx_sort[N];
    __shared__ unsigned long long s_glo[K], s_ghi[K];   // gm rows, original cols
    __shared__ unsigned long long s_rowlo[K], s_rowhi[K]; // permuted rows
    __shared__ int   s_pivot[K];
    __shared__ unsigned s_markw[4];
    __shared__ int   s_parity[K];
    __shared__ float s_pen[K];
    __shared__ float s_Lp[K];
    __shared__ unsigned long long s_pp[K];
    __shared__ float s_lut[8 * 256];
    __shared__ float s_bvw[8];
    __shared__ int   s_bqw[8];
    __shared__ float s_basew[2];
    __shared__ unsigned long long s_pw0w[2];
    __shared__ unsigned s_uw[2];
    __shared__ float s_base;
    __shared__ unsigned long long s_pw0, s_u, s_mwin, s_pwin;

    // ======== Phase 1 (task-parallel): llr load (warps 0-3) || gm pack (warps 4-7)
    float v = 0.0f;
    if (t < N) {
        v = llrs[b * N + t];
        v = fminf(fmaxf(v, -LLR_MAX), LLR_MAX);
        s_abs[t] = fabsf(v);
    } else {
        const int r = (t - 128) & 63;      // row
        const int h = (t - 128) >> 6;      // half: 0 = cols 0..63, 1 = cols 64..127
        const float4* rp = reinterpret_cast<const float4*>(gm + r * N + h * 64);
        unsigned long long w = 0ull;
        #pragma unroll
        for (int c4 = 0; c4 < 16; c4++) {
            float4 f = rp[c4];
            unsigned long long nib =
                  (unsigned long long)(f.x > 0.5f)
                | ((unsigned long long)(f.y > 0.5f) << 1)
                | ((unsigned long long)(f.z > 0.5f) << 2)
                | ((unsigned long long)(f.w > 0.5f) << 3);
            w |= nib << (c4 * 4);
        }
        if (h == 0) s_glo[r] = w; else s_ghi[r] = w;
    }
    if (t < 4) s_markw[t] = 0u;
    __syncthreads();

    // ======== Phase 2: split-rank stable argsort by descending |llr|
    if (t < N) {
        float a = s_abs[t];
        int r1 = 0;
        #pragma unroll 16
        for (int j = 0; j < 64; j++) {
            float aj = s_abs[j];
            r1 += (aj > a) || (aj == a && j < t);
        }
        s_rank2[t] = 0;           // placeholder; overwritten below by partner
        // keep r1 in register via recompute path: store in rank2 after partner sums
        // (partner writes its partial first; we add after barrier)
        // To avoid ordering hazard, partner uses a different array slot semantics:
        // we simply let partner write s_rank2, and we hold r1 locally.
        // store r1 temporarily in shared? Not needed: hold in register.
        // (dummy write above removed by using separate arrays below)
        s_rank2[t] = r1;          // r1 stored; partner accumulates via atomicAdd
    } else {
        // partner computes upper-half comparisons for position tt
        // delayed: done after barrier so r1 write is visible
    }
    __syncthreads();
    if (t >= N) {
        const int tt = t - 128;
        float a = s_abs[tt];
        int r2 = 0;
        #pragma unroll 16
        for (int j = 64; j < N; j++) {
            float aj = s_abs[j];
            r2 += (aj > a) || (aj == a && j < tt);
        }
        int rank = s_rank2[tt] + r2;
        s_idx_sort[rank] = tt;
    }
    __syncthreads();
    if (t < N) {
        // find my rank by locating where partner scattered? cheaper: recompute via idx
        // s_idx_sort[rank] = tt was set by partner; we need llr_sort too:
        // thread t holds v for original index t; partner knows rank. Store v via gather:
        // do gather from s_idx_sort instead: position p's value = llr[idx_sort[p]]
        s_llr_sort[t] = 0.0f; // overwritten below
    }
    __syncthreads();
    if (t < N) {
        int src = s_idx_sort[t];          // original index at sorted position t
        float sv = s_abs[src];            // |v|
        // need signed value: reload sign from llrs? keep a shared copy of clipped v
        // (use s_lut space temporarily? simpler: recompute from global is a LDG hit in L1)
        float raw = llrs[b * N + src];
        raw = fminf(fmaxf(raw, -LLR_MAX), LLR_MAX);
        (void)sv;
        s_llr_sort[t] = raw;
    }
    __syncthreads();

    // ======== Phase 3: permuted rows, 128 threads, registers only
    if (t < N) {
        const int r = t & 63;
        const int hh = t >> 6;            // 0: build lo word (pos 0..63), 1: hi word
        const unsigned long long rlo = s_glo[r];
        const unsigned long long rhi = s_ghi[r];
        unsigned long long w = 0ull;
        const int pbase = hh * 64;
        #pragma unroll 8
        for (int pi = 0; pi < 64; pi++) {
            int idx = s_idx_sort[pbase + pi];
            unsigned long long bit = (idx < 64) ? ((rlo >> idx) & 1ull)
                                                : ((rhi >> (idx - 64)) & 1ull);
            w |= bit << pi;
        }
        if (hh == 0) s_rowlo[r] = w; else s_rowhi[r] = w;
    }
    __syncthreads();

    // ======== Phase 4: single-warp register Gauss-Jordan over GF(2)
    if (t < 32) {
        unsigned long long r0lo = s_rowlo[t],      r0hi = s_rowhi[t];
        unsigned long long r1lo = s_rowlo[t + 32], r1hi = s_rowhi[t + 32];
        #pragma unroll 1
        for (int i = 0; i < K; i++) {
            const int src  = i & 31;
            const int slot = i >> 5;
            unsigned long long plo = __shfl_sync(FULLMASK, slot ? r1lo : r0lo, src);
            unsigned long long phi = __shfl_sync(FULLMASK, slot ? r1hi : r0hi, src);
            int p = plo ? (__ffsll(plo) - 1)
                        : (phi ? (64 + __ffsll(phi) - 1) : 0);
            if (lane == 0) s_pivot[i] = p;
            unsigned long long b0 = (p < 64) ? (r0lo >> p) : (r0hi >> (p - 64));
            unsigned long long b1 = (p < 64) ? (r1lo >> p) : (r1hi >> (p - 64));
            bool piv0 = (t == src) && (slot == 0);
            bool piv1 = (t == src) && (slot == 1);
            if ((b0 & 1ull) && !piv0) { r0lo ^= plo; r0hi ^= phi; }
            if ((b1 & 1ull) && !piv1) { r1lo ^= plo; r1hi ^= phi; }
        }
        s_rowlo[t] = r0lo;      s_rowhi[t] = r0hi;
        s_rowlo[t + 32] = r1lo; s_rowhi[t + 32] = r1hi;
    }
    __syncthreads();

    // ======== Phase 5: pivot marks + parity positions (prefix popcount)
    if (t < K) {
        int p = s_pivot[t];
        atomicOr(&s_markw[p >> 5], 1u << (p & 31));
    }
    __syncthreads();
    if (t < N) {
        unsigned w = s_markw[t >> 5];
        bool mk = (w >> (t & 31)) & 1u;
        int before = 0;
        #pragma unroll
        for (int ww = 0; ww < 4; ww++)
            if (ww < (t >> 5)) before += __popc(s_markw[ww]);
        before += __popc(w & ((1u << (t & 31)) - 1u));
        if (!mk) s_parity[t - before] = t;
    }
    __syncthreads();

    // ======== Phase 6: pen, Lp, pp + warp-reduced baseline (warps 0-1)
    if (t < K) {
        float Lt = s_llr_sort[s_pivot[t]];
        s_pen[t] = fabsf(Lt);
        s_Lp[t]  = s_llr_sort[s_parity[t]];
        unsigned long long rlo = s_rowlo[t], rhi = s_rowhi[t];
        unsigned long long pp = 0ull;
        #pragma unroll 8
        for (int j = 0; j < K; j++) {
            int pos = s_parity[j];
            unsigned long long bit = (pos < 64) ? ((rlo >> pos) & 1ull)
                                                : ((rhi >> (pos - 64)) & 1ull);
            pp |= bit << j;
        }
        s_pp[t] = pp;
        bool act = Lt > 0.0f;
        float val = act ? Lt : 0.0f;
        unsigned long long px = act ? pp : 0ull;
        #pragma unroll
        for (int o = 16; o > 0; o >>= 1) {
            val += __shfl_down_sync(FULLMASK, val, o);
            px  ^= __shfl_down_sync(FULLMASK, px, o);
        }
        unsigned ub = __ballot_sync(FULLMASK, act);
        if (lane == 0) { s_basew[wid] = val; s_pw0w[wid] = px; s_uw[wid] = ub; }
    }
    __syncthreads();
    if (t == 0) {
        s_base = s_basew[0] + s_basew[1];
        s_pw0  = s_pw0w[0] ^ s_pw0w[1];
        s_u    = (unsigned long long)s_uw[0] | ((unsigned long long)s_uw[1] << 32);
    }

    // ======== Phase 7: byte LUTs — tbl uniform per iteration, broadcast Lp loads
    {
        const unsigned bb = (unsigned)(t & 255);
        #pragma unroll
        for (int tbl = 0; tbl < 8; tbl++) {
            float s = 0.0f;
            #pragma unroll
            for (int bp = 0; bp < 8; bp++) {
                float lp = s_Lp[tbl * 8 + bp];      // uniform broadcast
                if (bb & (1u << bp)) s += lp;
            }
            s_lut[tbl * 256 + bb] = s;
        }
    }
    __syncthreads();

    // ======== Phase 8: candidate scan, 8-9 candidates per thread, contiguous q
    const float base = s_base;
    const unsigned long long pw0 = s_pw0;
    const int cnt = (t < 33) ? 9 : 8;       // 33*9 + 223*8 = 2081
    int q = t * 8 + min(t, 33);
    float bestv = -3.0e38f;
    int   bestq = 0x7fffffff;
    int pi = 0, pj = 0;
    bool init = false;
    for (int si = 0; si < cnt; si++, q++) {
        float sc;
        unsigned long long pw;
        if (q == 0) {
            sc = base; pw = pw0;
        } else if (q <= K) {
            sc = base - s_pen[q - 1];
            pw = pw0 ^ s_pp[q - 1];
        } else {
            if (!init) {
                int r = q - (K + 1);
                pi = 0; int c = K - 1;
                while (r >= c) { r -= c; c--; pi++; }
                pj = pi + 1 + r;
                init = true;
            } else {
                pj++;
                if (pj == K) { pi++; pj = pi + 1; }
            }
            sc = base - s_pen[pi] - s_pen[pj];
            pw = pw0 ^ s_pp[pi] ^ s_pp[pj];
        }
        #pragma unroll
        for (int bkt = 0; bkt < 8; bkt++)
            sc += s_lut[bkt * 256 + (int)((pw >> (bkt * 8)) & 0xffull)];
        if (sc > bestv) { bestv = sc; bestq = q; }  // strict > keeps earliest q
    }

    // warp reduce: max over (v, -q) — total order, tree-safe
    #pragma unroll
    for (int o = 16; o > 0; o >>= 1) {
        float ov = __shfl_down_sync(FULLMASK, bestv, o);
        int   oq = __shfl_down_sync(FULLMASK, bestq, o);
        if (ov > bestv || (ov == bestv && oq < bestq)) { bestv = ov; bestq = oq; }
    }
    if (lane == 0) { s_bvw[wid] = bestv; s_bqw[wid] = bestq; }
    __syncthreads();

    // ======== Phase 9: final combine + decode winner
    if (t == 0) {
        float bv = s_bvw[0]; int bq = s_bqw[0];
        #pragma unroll
        for (int w = 1; w < 8; w++) {
            if (s_bvw[w] > bv || (s_bvw[w] == bv && s_bqw[w] < bq)) {
                bv = s_bvw[w]; bq = s_bqw[w];
            }
        }
        unsigned long long flips = 0ull;
        if (bq >= 1 && bq <= K) {
            flips = 1ull << (bq - 1);
        } else if (bq > K) {
            int r = bq - (K + 1);
            int i2 = 0, c = K - 1;
            while (r >= c) { r -= c; c--; i2++; }
            int j2 = i2 + 1 + r;
            flips = (1ull << i2) | (1ull << j2);
        }
        unsigned long long pw = s_pw0, f = flips;
        while (f) {
            int i2 = __ffsll(f) - 1;
            pw ^= s_pp[i2];
            f &= f - 1;
        }
        s_mwin = s_u ^ flips;
        s_pwin = pw;
    }
    __syncthreads();

    // ======== Phase 10: scatter to original column order
    if (t < K) {
        int orig = s_idx_sort[s_pivot[t]];
        out[b * N + orig] = (float)((s_mwin >> t) & 1ull);
    } else if (t < N) {
        int j2 = t - K;
        int orig = s_idx_sort[s_parity[j2]];
        out[b * N + orig] = (float)((s_pwin >> j2) & 1ull);
    }
}

extern "C" void kernel_launch(void* const* d_in, const int* in_sizes, int n_in,
                              void* d_out, int out_size)
{
    const float* llrs = (const float*)d_in[0]; // (bs, 128) float32
    const float* gm   = (const float*)d_in[1]; // (64, 128) float32
    float* out = (float*)d_out;                // (bs, 128) float32
    int bs = in_sizes[0] / N;
    osd_kernel<<<bs, 256>>>(llrs, gm, out);
}